// round 1
// baseline (speedup 1.0000x reference)
#include <cuda_runtime.h>
#include <cuda_fp16.h>
#include <mma.h>
#include <math.h>

using namespace nvcuda;

// Problem dims (fixed by the problem instance)
#define T_TOK   16384
#define DDIM    1024
#define HDIM    4096
#define NEXP    8
#define NASSIGN (T_TOK * 2)     // top-2, distinct experts per token
#define MAX_TILES 264           // worst case sum ceil(cnt_e/128) <= 2T/128 + 8

// ---------------- static device scratch (no runtime allocation allowed) ----
__device__ __half g_xh [(size_t)T_TOK * DDIM];          // x in fp16
__device__ __half g_w1h[(size_t)NEXP * DDIM * HDIM];    // w1 fp16
__device__ __half g_w2h[(size_t)NEXP * HDIM * DDIM];    // w2 fp16
__device__ __half g_hbuf[(size_t)NASSIGN * HDIM];       // gelu(x@w1) per assignment
__device__ float  g_y  [(size_t)NASSIGN * DDIM];        // h@w2 + b2 per assignment

__device__ int   g_cnt[NEXP];
__device__ int   g_fill[NEXP];
__device__ int   g_off[NEXP];
__device__ int   g_tok_e[T_TOK * 2];
__device__ float g_tok_w[T_TOK * 2];
__device__ int   g_rows[NASSIGN];       // assignment slot -> token index
__device__ int   g_slot_of[T_TOK * 2];  // token,rank -> slot
__device__ int   g_tile_e[MAX_TILES + 8];
__device__ int   g_tile_r[MAX_TILES + 8];
__device__ int   g_nt;

// ---------------- helpers ---------------------------------------------------
__device__ __forceinline__ void cp16(void* s, const void* g, bool v) {
    unsigned sa = (unsigned)__cvta_generic_to_shared(s);
    int sz = v ? 16 : 0;
    asm volatile("cp.async.cg.shared.global [%0], [%1], 16, %2;\n"
                 :: "r"(sa), "l"(g), "r"(sz) : "memory");
}
__device__ __forceinline__ void cp_commit() {
    asm volatile("cp.async.commit_group;\n" ::: "memory");
}
__device__ __forceinline__ void cp_wait0() {
    asm volatile("cp.async.wait_group 0;\n" ::: "memory");
}
__device__ __forceinline__ float gelu_exact(float x) {
    return 0.5f * x * (1.0f + erff(x * 0.70710678118654752f));
}

// ---------------- fp32 -> fp16 conversion ------------------------------------
__global__ void f2h_kernel(const float4* __restrict__ in, __half2* __restrict__ out, int n4) {
    int i = blockIdx.x * blockDim.x + threadIdx.x;
    if (i < n4) {
        float4 v = in[i];
        out[2 * i]     = __floats2half2_rn(v.x, v.y);
        out[2 * i + 1] = __floats2half2_rn(v.z, v.w);
    }
}

__global__ void zero_kernel() {
    int i = threadIdx.x;
    if (i < NEXP) { g_cnt[i] = 0; g_fill[i] = 0; }
}

// ---------------- router: logits + softmax + top-2 --------------------------
__global__ void router_kernel(const float* __restrict__ x,
                              const float* __restrict__ rw,
                              float* __restrict__ logits_out) {
    int gwarp = (blockIdx.x * blockDim.x + threadIdx.x) >> 5;
    int lane  = threadIdx.x & 31;
    if (gwarp >= T_TOK) return;
    const float* xr = x + (size_t)gwarp * DDIM;
    float acc[NEXP];
#pragma unroll
    for (int e = 0; e < NEXP; e++) acc[e] = 0.f;
    for (int d = lane; d < DDIM; d += 32) {
        float xv = xr[d];
        const float* r = rw + d * NEXP;
#pragma unroll
        for (int e = 0; e < NEXP; e++) acc[e] += xv * r[e];
    }
#pragma unroll
    for (int e = 0; e < NEXP; e++)
#pragma unroll
        for (int o = 16; o > 0; o >>= 1)
            acc[e] += __shfl_xor_sync(0xffffffffu, acc[e], o);

    if (lane == 0) {
#pragma unroll
        for (int e = 0; e < NEXP; e++) logits_out[(size_t)gwarp * NEXP + e] = acc[e];
        float m = acc[0];
#pragma unroll
        for (int e = 1; e < NEXP; e++) m = fmaxf(m, acc[e]);
        float p[NEXP]; float s = 0.f;
#pragma unroll
        for (int e = 0; e < NEXP; e++) { p[e] = expf(acc[e] - m); s += p[e]; }
        float inv = 1.f / s;
        // top-1 (lowest index on tie: strict >)
        int e0 = 0; float p0 = p[0];
#pragma unroll
        for (int e = 1; e < NEXP; e++) if (p[e] > p0) { p0 = p[e]; e0 = e; }
        // top-2
        int e1 = -1; float p1 = -1.f;
#pragma unroll
        for (int e = 0; e < NEXP; e++)
            if (e != e0 && p[e] > p1) { p1 = p[e]; e1 = e; }
        g_tok_e[2 * gwarp]     = e0;
        g_tok_e[2 * gwarp + 1] = e1;
        g_tok_w[2 * gwarp]     = p0 * inv;
        g_tok_w[2 * gwarp + 1] = p1 * inv;
        atomicAdd(&g_cnt[e0], 1);
        atomicAdd(&g_cnt[e1], 1);
    }
}

// ---------------- scan + tile metadata (single thread, trivial) --------------
__global__ void scan_kernel() {
    int off = 0, nt = 0;
    for (int e = 0; e < NEXP; e++) {
        g_off[e] = off;
        int c = g_cnt[e];
        off += c;
        int t = (c + 127) >> 7;
        for (int i = 0; i < t; i++) { g_tile_e[nt] = e; g_tile_r[nt] = i << 7; nt++; }
    }
    g_nt = nt;
}

// ---------------- compact assignment -----------------------------------------
__global__ void assign_kernel() {
    int t = blockIdx.x * blockDim.x + threadIdx.x;
    if (t >= T_TOK) return;
#pragma unroll
    for (int k = 0; k < 2; k++) {
        int e = g_tok_e[2 * t + k];
        int p = atomicAdd(&g_fill[e], 1);
        int s = g_off[e] + p;
        g_rows[s] = t;
        g_slot_of[2 * t + k] = s;
    }
}

// ---------------- grouped GEMM (wmma fp16, fp32 accum) ------------------------
// MODE 0: A = g_xh gathered via g_rows, out = gelu(acc + b1) -> g_hbuf (fp16)
// MODE 1: A = g_hbuf (contiguous slots), out = acc + b2 -> g_y (fp32)
// CTA tile 128x128, BK=32, 8 warps (2x4), warp tile 64x32, double buffered cp.async.
#define SMEM_A_BYTES (2 * 128 * 40 * 2)
#define SMEM_B_BYTES (2 * 32 * 136 * 2)
#define SMEM_C_BYTES (128 * 132 * 4)
#define SMEM_TOTAL_BYTES (SMEM_A_BYTES + SMEM_B_BYTES + SMEM_C_BYTES)

template <int MODE>
__global__ void __launch_bounds__(256, 1)
gemm_kernel(const __half* __restrict__ Abase,
            const __half* __restrict__ Bbase,
            const float*  __restrict__ bvec,
            int K, int N) {
    extern __shared__ char smem_raw[];
    __half* sA = (__half*)smem_raw;                               // [2][128][40]
    __half* sB = (__half*)(smem_raw + SMEM_A_BYTES);              // [2][32][136]
    float*  sC = (float*)(smem_raw + SMEM_A_BYTES + SMEM_B_BYTES);// [128][132]

    int tile = blockIdx.x;
    if (tile >= g_nt) return;
    int e     = g_tile_e[tile];
    int r0    = g_tile_r[tile];
    int slot0 = g_off[e] + r0;
    int rows  = g_cnt[e] - r0; if (rows > 128) rows = 128;
    int n0    = blockIdx.y * 128;

    int tid  = threadIdx.x;
    int warp = tid >> 5;
    int wm   = warp >> 2;      // 0..1
    int wn   = warp & 3;       // 0..3

    // A load mapping: thread -> rows (tid>>2, +64), 16B chunk (tid&3)
    int rA = tid >> 2;
    int cA = (tid & 3) * 8;
    bool vA0 = rA < rows, vA1 = (rA + 64) < rows;
    const __half* gA0; const __half* gA1;
    if (MODE == 0) {
        int t0 = vA0 ? g_rows[slot0 + rA]      : 0;
        int t1 = vA1 ? g_rows[slot0 + rA + 64] : 0;
        gA0 = Abase + (size_t)t0 * K + cA;
        gA1 = Abase + (size_t)t1 * K + cA;
    } else {
        int s0 = slot0 + rA;      if (s0 >= NASSIGN) s0 = NASSIGN - 1;
        int s1 = slot0 + rA + 64; if (s1 >= NASSIGN) s1 = NASSIGN - 1;
        gA0 = Abase + (size_t)s0 * K + cA;
        gA1 = Abase + (size_t)s1 * K + cA;
    }
    // B load mapping: thread -> rows (tid>>4, +16), chunk (tid&15)
    int rB = tid >> 4;
    int cB = (tid & 15) * 8;
    const __half* gB0 = Bbase + (size_t)e * K * N + (size_t)rB * N + n0 + cB;
    const __half* gB1 = gB0 + (size_t)16 * N;

    auto load_stage = [&](int st, int k0) {
        cp16(&sA[(size_t)(st * 128 + rA) * 40 + cA],      gA0 + k0, vA0);
        cp16(&sA[(size_t)(st * 128 + rA + 64) * 40 + cA], gA1 + k0, vA1);
        cp16(&sB[(size_t)(st * 32 + rB) * 136 + cB],      gB0 + (size_t)k0 * N, true);
        cp16(&sB[(size_t)(st * 32 + rB + 16) * 136 + cB], gB1 + (size_t)k0 * N, true);
    };

    wmma::fragment<wmma::accumulator, 16, 16, 16, float> acc[4][2];
#pragma unroll
    for (int mi = 0; mi < 4; mi++)
#pragma unroll
        for (int ni = 0; ni < 2; ni++) wmma::fill_fragment(acc[mi][ni], 0.f);

    int nk = K >> 5;
    load_stage(0, 0);
    cp_commit();
    for (int kt = 0; kt < nk; kt++) {
        cp_wait0();
        __syncthreads();
        if (kt + 1 < nk) { load_stage((kt + 1) & 1, (kt + 1) << 5); cp_commit(); }
        int st = kt & 1;
#pragma unroll
        for (int kk = 0; kk < 2; kk++) {
            wmma::fragment<wmma::matrix_a, 16, 16, 16, __half, wmma::row_major> fa[4];
            wmma::fragment<wmma::matrix_b, 16, 16, 16, __half, wmma::row_major> fb[2];
#pragma unroll
            for (int mi = 0; mi < 4; mi++)
                wmma::load_matrix_sync(fa[mi],
                    &sA[(size_t)(st * 128 + wm * 64 + mi * 16) * 40 + kk * 16], 40);
#pragma unroll
            for (int ni = 0; ni < 2; ni++)
                wmma::load_matrix_sync(fb[ni],
                    &sB[(size_t)(st * 32 + kk * 16) * 136 + wn * 32 + ni * 16], 136);
#pragma unroll
            for (int mi = 0; mi < 4; mi++)
#pragma unroll
                for (int ni = 0; ni < 2; ni++)
                    wmma::mma_sync(acc[mi][ni], fa[mi], fb[ni], acc[mi][ni]);
        }
    }
    __syncthreads();

    // stage accumulators to smem
#pragma unroll
    for (int mi = 0; mi < 4; mi++)
#pragma unroll
        for (int ni = 0; ni < 2; ni++)
            wmma::store_matrix_sync(&sC[(size_t)(wm * 64 + mi * 16) * 132 + wn * 32 + ni * 16],
                                    acc[mi][ni], 132, wmma::mem_row_major);
    __syncthreads();

    // epilogue: bias + (gelu & fp16 store) or fp32 store
    for (int i = tid; i < 128 * 32; i += 256) {
        int r = i >> 5;
        int c = (i & 31) << 2;
        if (r >= rows) continue;
        float4 v = *(const float4*)&sC[(size_t)r * 132 + c];
        float4 bv = *(const float4*)&bvec[(size_t)e * N + n0 + c];
        v.x += bv.x; v.y += bv.y; v.z += bv.z; v.w += bv.w;
        if (MODE == 0) {
            v.x = gelu_exact(v.x); v.y = gelu_exact(v.y);
            v.z = gelu_exact(v.z); v.w = gelu_exact(v.w);
            __half2 h01 = __floats2half2_rn(v.x, v.y);
            __half2 h23 = __floats2half2_rn(v.z, v.w);
            __half* op = g_hbuf + (size_t)(slot0 + r) * HDIM + n0 + c;
            *(__half2*)op = h01;
            *(__half2*)(op + 2) = h23;
        } else {
            float* op = g_y + (size_t)(slot0 + r) * DDIM + n0 + c;
            *(float4*)op = v;
        }
    }
}

// ---------------- combine: out = bias + w0*y[s0] + w1*y[s1] -------------------
__global__ void combine_kernel(const float* __restrict__ bias, float* __restrict__ out) {
    int i = blockIdx.x * blockDim.x + threadIdx.x;
    if (i >= T_TOK * (DDIM / 4)) return;
    int t = i >> 8;               // DDIM/4 = 256
    int c = (i & 255) << 2;
    float w0 = g_tok_w[2 * t];
    float w1 = g_tok_w[2 * t + 1];
    int   s0 = g_slot_of[2 * t];
    int   s1 = g_slot_of[2 * t + 1];
    float4 y0 = *(const float4*)&g_y[(size_t)s0 * DDIM + c];
    float4 y1 = *(const float4*)&g_y[(size_t)s1 * DDIM + c];
    float4 bv = *(const float4*)&bias[c];
    float4 o;
    o.x = bv.x + w0 * y0.x + w1 * y1.x;
    o.y = bv.y + w0 * y0.y + w1 * y1.y;
    o.z = bv.z + w0 * y0.z + w1 * y1.z;
    o.w = bv.w + w0 * y0.w + w1 * y1.w;
    *(float4*)&out[(size_t)t * DDIM + c] = o;
}

// ---------------- launch ------------------------------------------------------
extern "C" void kernel_launch(void* const* d_in, const int* in_sizes, int n_in,
                              void* d_out, int out_size) {
    const float* x    = (const float*)d_in[0];
    const float* rw   = (const float*)d_in[1];
    const float* w1   = (const float*)d_in[2];
    const float* b1   = (const float*)d_in[3];
    const float* w2   = (const float*)d_in[4];
    const float* b2   = (const float*)d_in[5];
    const float* bias = (const float*)d_in[6];
    float* out    = (float*)d_out;
    float* logits = out + (size_t)T_TOK * DDIM;

    void *p_xh, *p_w1h, *p_w2h, *p_hbuf;
    cudaGetSymbolAddress(&p_xh,   g_xh);
    cudaGetSymbolAddress(&p_w1h,  g_w1h);
    cudaGetSymbolAddress(&p_w2h,  g_w2h);
    cudaGetSymbolAddress(&p_hbuf, g_hbuf);

    cudaFuncSetAttribute(gemm_kernel<0>, cudaFuncAttributeMaxDynamicSharedMemorySize, SMEM_TOTAL_BYTES);
    cudaFuncSetAttribute(gemm_kernel<1>, cudaFuncAttributeMaxDynamicSharedMemorySize, SMEM_TOTAL_BYTES);

    // fp32 -> fp16 conversions
    {
        int n4 = (T_TOK * DDIM) / 4;
        f2h_kernel<<<(n4 + 255) / 256, 256>>>((const float4*)x, (__half2*)p_xh, n4);
    }
    {
        int n4 = (NEXP * DDIM * HDIM) / 4;
        f2h_kernel<<<(n4 + 255) / 256, 256>>>((const float4*)w1, (__half2*)p_w1h, n4);
        f2h_kernel<<<(n4 + 255) / 256, 256>>>((const float4*)w2, (__half2*)p_w2h, n4);
    }

    zero_kernel<<<1, 32>>>();
    router_kernel<<<T_TOK / 8, 256>>>(x, rw, logits);
    scan_kernel<<<1, 1>>>();
    assign_kernel<<<T_TOK / 256, 256>>>();

    // GEMM1: [cnt_e,1024] x [1024,4096] -> gelu -> hbuf
    gemm_kernel<0><<<dim3(MAX_TILES, HDIM / 128), 256, SMEM_TOTAL_BYTES>>>(
        (const __half*)p_xh, (const __half*)p_w1h, b1, DDIM, HDIM);
    // GEMM2: [cnt_e,4096] x [4096,1024] -> y
    gemm_kernel<1><<<dim3(MAX_TILES, DDIM / 128), 256, SMEM_TOTAL_BYTES>>>(
        (const __half*)p_hbuf, (const __half*)p_w2h, b2, HDIM, DDIM);

    combine_kernel<<<(T_TOK * (DDIM / 4) + 255) / 256, 256>>>(bias, out);
}